// round 1
// baseline (speedup 1.0000x reference)
#include <cuda_runtime.h>

#define NB 256
#define NT 64
#define ND 2048
#define THRESHOLD 0.99f
#define EPSILON 0.01f

// Kernel 1: per-batch ACT halting weights + ponder cost.
// One thread per batch. All data (B*T floats x2 = 128 KB) is L2-resident.
__global__ void act_weights_kernel(const float* __restrict__ halt_probs,
                                   const float* __restrict__ step_weights,
                                   float* __restrict__ weights_out,
                                   float* __restrict__ ponder_out) {
    int b = blockIdx.x * blockDim.x + threadIdx.x;
    if (b >= NB) return;

    const float* p  = halt_probs   + (size_t)b * NT;   // halt_probs[b, t, 0]
    const float* sw = step_weights + (size_t)b * NT;

    // Pass A: cumsum, find first index where cum >= THRESHOLD.
    float cum = 0.0f;
    int   h = NT - 1;
    bool  found = false;
    float cum_at = 0.0f, p_at = 0.0f, last_p = 0.0f;
    for (int t = 0; t < NT; t++) {
        float pt = p[t];
        cum += pt;
        if (!found && cum >= THRESHOLD) {
            found = true; h = t; cum_at = cum; p_at = pt;
        }
        last_p = pt;
    }
    if (!found) { cum_at = cum; p_at = last_p; }  // h = T-1 fallback
    float remaining = 1.0f - cum_at + p_at;

    // Pass B: unnormalized weighted sum.
    float sum = 0.0f;
    for (int t = 0; t < NT; t++) {
        float w = (t < h) ? p[t] : ((t == h) ? remaining : 0.0f);
        sum += w * sw[t];
    }
    float inv = 1.0f / fmaxf(sum, EPSILON);

    // Pass C: normalized weights + ponder cost.
    float ponder = 0.0f;
    for (int t = 0; t < NT; t++) {
        float w = (t < h) ? p[t] : ((t == h) ? remaining : 0.0f);
        w = w * sw[t] * inv;
        weights_out[(size_t)b * NT + t] = w;
        ponder += w * (float)(t + 1);
    }
    ponder_out[b] = ponder;
}

// Kernel 2: final_output[b, d] = sum_t weights[b, t] * outputs[b, t, d].
// HBM-bound streaming of outputs (134 MB). float4 vectorized, coalesced.
// grid = (ND / (256*4), NB), block = 256 threads.
__global__ void act_reduce_kernel(const float* __restrict__ outputs,
                                  const float* __restrict__ weights,
                                  float* __restrict__ final_out) {
    __shared__ float w[NT];
    int b = blockIdx.y;
    if (threadIdx.x < NT) w[threadIdx.x] = weights[(size_t)b * NT + threadIdx.x];
    __syncthreads();

    int idx = blockIdx.x * blockDim.x + threadIdx.x;       // float4 index within D
    const float4* src = (const float4*)(outputs + (size_t)b * NT * ND);
    const int row4 = ND / 4;

    float4 acc = make_float4(0.f, 0.f, 0.f, 0.f);
    #pragma unroll 8
    for (int t = 0; t < NT; t++) {
        float4 v = src[(size_t)t * row4 + idx];
        float wt = w[t];
        acc.x = fmaf(wt, v.x, acc.x);
        acc.y = fmaf(wt, v.y, acc.y);
        acc.z = fmaf(wt, v.z, acc.z);
        acc.w = fmaf(wt, v.w, acc.w);
    }
    ((float4*)(final_out + (size_t)b * ND))[idx] = acc;
}

extern "C" void kernel_launch(void* const* d_in, const int* in_sizes, int n_in,
                              void* d_out, int out_size) {
    const float* halt_probs   = (const float*)d_in[0];  // [B, T, 1]
    const float* outputs      = (const float*)d_in[1];  // [B, T, D]
    const float* step_weights = (const float*)d_in[2];  // [B, T]

    // Output tuple flattened in order: final_output [B*D], ponder_cost [B], weights [B*T]
    float* final_out  = (float*)d_out;
    float* ponder_out = final_out + (size_t)NB * ND;
    float* weights_out = ponder_out + NB;

    act_weights_kernel<<<(NB + 255) / 256, 256>>>(halt_probs, step_weights,
                                                  weights_out, ponder_out);

    dim3 grid(ND / (256 * 4), NB);
    act_reduce_kernel<<<grid, 256>>>(outputs, weights_out, final_out);
}

// round 2
// speedup vs baseline: 2.3419x; 2.3419x over previous
#include <cuda_runtime.h>

#define NB 256
#define NT 64
#define ND 2048
#define THRESHOLD 0.99f
#define EPSILON 0.01f

// Fused kernel. grid = (4, NB), block = 128 threads.
// Phase 1 (warp 0): compute ACT weights for batch b via warp scan -> smem.
//                   blockIdx.x==0 also writes weights + ponder_cost to gmem.
// Phase 2 (all):    stream outputs[b, :, chunk] and accumulate final_output.
__global__ void __launch_bounds__(128) act_fused_kernel(
        const float* __restrict__ halt_probs,
        const float* __restrict__ outputs,
        const float* __restrict__ step_weights,
        float* __restrict__ final_out,
        float* __restrict__ ponder_out,
        float* __restrict__ weights_out) {
    __shared__ float wsh[NT];
    const int b = blockIdx.y;
    const unsigned FULL = 0xffffffffu;

    if (threadIdx.x < 32) {
        const int lane = threadIdx.x;
        const float* p  = halt_probs   + (size_t)b * NT;
        const float* sw = step_weights + (size_t)b * NT;

        // Load both halves of the T=64 row (coalesced).
        float a = p[lane];          // t = lane
        float c = p[lane + 32];     // t = lane + 32

        // Inclusive scan of first half.
        float sa = a;
        #pragma unroll
        for (int off = 1; off < 32; off <<= 1) {
            float v = __shfl_up_sync(FULL, sa, off);
            if (lane >= off) sa += v;
        }
        float tot_a = __shfl_sync(FULL, sa, 31);
        // Inclusive scan of second half, offset by first-half total.
        float sc = c;
        #pragma unroll
        for (int off = 1; off < 32; off <<= 1) {
            float v = __shfl_up_sync(FULL, sc, off);
            if (lane >= off) sc += v;
        }
        sc += tot_a;

        // First t with cumsum >= THRESHOLD (fallback T-1).
        unsigned m1 = __ballot_sync(FULL, sa >= THRESHOLD);
        unsigned m2 = __ballot_sync(FULL, sc >= THRESHOLD);
        int h;
        if (m1)      h = __ffs(m1) - 1;
        else if (m2) h = 32 + __ffs(m2) - 1;
        else         h = NT - 1;

        float cum_at, p_at;
        if (h < 32) {
            cum_at = __shfl_sync(FULL, sa, h);
            p_at   = __shfl_sync(FULL, a,  h);
        } else {
            cum_at = __shfl_sync(FULL, sc, h - 32);
            p_at   = __shfl_sync(FULL, c,  h - 32);
        }
        float remaining = 1.0f - cum_at + p_at;

        // Raw weights * step_weights for this lane's two t positions.
        float sw_a = sw[lane], sw_c = sw[lane + 32];
        int t0 = lane, t1 = lane + 32;
        float w0 = (t0 < h) ? a : ((t0 == h) ? remaining : 0.0f);
        float w1 = (t1 < h) ? c : ((t1 == h) ? remaining : 0.0f);
        w0 *= sw_a;
        w1 *= sw_c;

        // Warp sum of w0 + w1.
        float s = w0 + w1;
        #pragma unroll
        for (int off = 16; off > 0; off >>= 1)
            s += __shfl_xor_sync(FULL, s, off);
        float inv = 1.0f / fmaxf(s, EPSILON);

        w0 *= inv;
        w1 *= inv;
        wsh[t0] = w0;
        wsh[t1] = w1;

        if (blockIdx.x == 0) {
            weights_out[(size_t)b * NT + t0] = w0;
            weights_out[(size_t)b * NT + t1] = w1;
            // ponder = sum_t w[t] * (t+1)
            float pc = w0 * (float)(t0 + 1) + w1 * (float)(t1 + 1);
            #pragma unroll
            for (int off = 16; off > 0; off >>= 1)
                pc += __shfl_xor_sync(FULL, pc, off);
            if (lane == 0) ponder_out[b] = pc;
        }
    }
    __syncthreads();

    // Phase 2: each thread owns one float4 lane of D.
    const int idx = blockIdx.x * blockDim.x + threadIdx.x;   // float4 index in D
    const float4* src = (const float4*)(outputs + (size_t)b * NT * ND);
    const int row4 = ND / 4;

    float4 acc = make_float4(0.f, 0.f, 0.f, 0.f);
    #pragma unroll 8
    for (int t = 0; t < NT; t++) {
        float4 v = __ldcs(&src[(size_t)t * row4 + idx]);
        float wt = wsh[t];
        acc.x = fmaf(wt, v.x, acc.x);
        acc.y = fmaf(wt, v.y, acc.y);
        acc.z = fmaf(wt, v.z, acc.z);
        acc.w = fmaf(wt, v.w, acc.w);
    }
    ((float4*)(final_out + (size_t)b * ND))[idx] = acc;
}

extern "C" void kernel_launch(void* const* d_in, const int* in_sizes, int n_in,
                              void* d_out, int out_size) {
    const float* halt_probs   = (const float*)d_in[0];  // [B, T, 1]
    const float* outputs      = (const float*)d_in[1];  // [B, T, D]
    const float* step_weights = (const float*)d_in[2];  // [B, T]

    float* final_out   = (float*)d_out;                 // [B, D]
    float* ponder_out  = final_out + (size_t)NB * ND;   // [B]
    float* weights_out = ponder_out + NB;               // [B, T]

    dim3 grid(ND / (128 * 4), NB);                      // (4, 256)
    act_fused_kernel<<<grid, 128>>>(halt_probs, outputs, step_weights,
                                    final_out, ponder_out, weights_out);
}

// round 5
// speedup vs baseline: 2.5510x; 1.0893x over previous
#include <cuda_runtime.h>

#define NB 256
#define NT 64
#define ND 2048
#define THRESHOLD 0.99f
#define EPSILON 0.01f

// Fused kernel. grid = (4, NB), block = 128 threads.
// Phase 1 (warp 0): ACT weights for batch b via warp scan -> smem.
//                   blockIdx.x==0 also writes weights + ponder_cost to gmem.
// Phase 2 (all):    stream outputs[b, :, chunk] with forced MLP=8, accumulate.
__global__ void __launch_bounds__(128) act_fused_kernel(
        const float* __restrict__ halt_probs,
        const float* __restrict__ outputs,
        const float* __restrict__ step_weights,
        float* __restrict__ final_out,
        float* __restrict__ ponder_out,
        float* __restrict__ weights_out) {
    __shared__ float wsh[NT];
    const int b = blockIdx.y;
    const unsigned FULL = 0xffffffffu;

    if (threadIdx.x < 32) {
        const int lane = threadIdx.x;
        const float* p  = halt_probs   + (size_t)b * NT;
        const float* sw = step_weights + (size_t)b * NT;

        float a = p[lane];          // t = lane
        float c = p[lane + 32];     // t = lane + 32

        // Inclusive scan over 64 elements (two 32-lane halves).
        float sa = a;
        #pragma unroll
        for (int off = 1; off < 32; off <<= 1) {
            float v = __shfl_up_sync(FULL, sa, off);
            if (lane >= off) sa += v;
        }
        float tot_a = __shfl_sync(FULL, sa, 31);
        float sc = c;
        #pragma unroll
        for (int off = 1; off < 32; off <<= 1) {
            float v = __shfl_up_sync(FULL, sc, off);
            if (lane >= off) sc += v;
        }
        sc += tot_a;

        // First t with cumsum >= THRESHOLD (fallback T-1).
        unsigned m1 = __ballot_sync(FULL, sa >= THRESHOLD);
        unsigned m2 = __ballot_sync(FULL, sc >= THRESHOLD);
        int h;
        if (m1)      h = __ffs(m1) - 1;
        else if (m2) h = 32 + __ffs(m2) - 1;
        else         h = NT - 1;

        float cum_at, p_at;
        if (h < 32) {
            cum_at = __shfl_sync(FULL, sa, h);
            p_at   = __shfl_sync(FULL, a,  h);
        } else {
            cum_at = __shfl_sync(FULL, sc, h - 32);
            p_at   = __shfl_sync(FULL, c,  h - 32);
        }
        float remaining = 1.0f - cum_at + p_at;

        float sw_a = sw[lane], sw_c = sw[lane + 32];
        int t0 = lane, t1 = lane + 32;
        float w0 = (t0 < h) ? a : ((t0 == h) ? remaining : 0.0f);
        float w1 = (t1 < h) ? c : ((t1 == h) ? remaining : 0.0f);
        w0 *= sw_a;
        w1 *= sw_c;

        float s = w0 + w1;
        #pragma unroll
        for (int off = 16; off > 0; off >>= 1)
            s += __shfl_xor_sync(FULL, s, off);
        float inv = 1.0f / fmaxf(s, EPSILON);

        w0 *= inv;
        w1 *= inv;
        wsh[t0] = w0;
        wsh[t1] = w1;

        if (blockIdx.x == 0) {
            weights_out[(size_t)b * NT + t0] = w0;
            weights_out[(size_t)b * NT + t1] = w1;
            float pc = w0 * (float)(t0 + 1) + w1 * (float)(t1 + 1);
            #pragma unroll
            for (int off = 16; off > 0; off >>= 1)
                pc += __shfl_xor_sync(FULL, pc, off);
            if (lane == 0) ponder_out[b] = pc;
        }
    }
    __syncthreads();

    // Phase 2: each thread owns one float4 lane of D. Forced MLP=8:
    // batch 8 independent LDG.128 before any consumer.
    const int idx = blockIdx.x * blockDim.x + threadIdx.x;   // float4 index in D
    const int row4 = ND / 4;
    const float4* src = (const float4*)(outputs + (size_t)b * NT * ND) + idx;

    float4 acc = make_float4(0.f, 0.f, 0.f, 0.f);
    #pragma unroll
    for (int tb = 0; tb < NT; tb += 8) {
        float4 v[8];
        #pragma unroll
        for (int i = 0; i < 8; i++)
            v[i] = __ldcs(src + (size_t)(tb + i) * row4);
        #pragma unroll
        for (int i = 0; i < 8; i++) {
            float wt = wsh[tb + i];
            acc.x = fmaf(wt, v[i].x, acc.x);
            acc.y = fmaf(wt, v[i].y, acc.y);
            acc.z = fmaf(wt, v[i].z, acc.z);
            acc.w = fmaf(wt, v[i].w, acc.w);
        }
    }
    ((float4*)(final_out + (size_t)b * ND))[idx] = acc;
}

extern "C" void kernel_launch(void* const* d_in, const int* in_sizes, int n_in,
                              void* d_out, int out_size) {
    const float* halt_probs   = (const float*)d_in[0];  // [B, T, 1]
    const float* outputs      = (const float*)d_in[1];  // [B, T, D]
    const float* step_weights = (const float*)d_in[2];  // [B, T]

    float* final_out   = (float*)d_out;                 // [B, D]
    float* ponder_out  = final_out + (size_t)NB * ND;   // [B]
    float* weights_out = ponder_out + NB;               // [B, T]

    dim3 grid(ND / (128 * 4), NB);                      // (4, 256)
    act_fused_kernel<<<grid, 128>>>(halt_probs, outputs, step_weights,
                                    final_out, ponder_out, weights_out);
}